// round 4
// baseline (speedup 1.0000x reference)
#include <cuda_runtime.h>
#include <cstddef>

#define NMAX   400000
#define FDIM   128
#define KNBR   5
#define NEDGE  (NMAX * KNBR)

// Scratch (static device allocations):
__device__ int           g_deg[NMAX];            // live in-degree per dest
__device__ int           g_off[NMAX];            // CSR offset; fill turns it into end-cursor
__device__ unsigned char g_flag[NMAX];           // dest selected?
__device__ int           g_total;                // scan base counter
__device__ int2          g_edges[NEDGE];         // (src, weight-as-bits)
__device__ float         g_row[(size_t)NMAX * FDIM]; // normalized rows (flagged dests only)

// ---------------------------------------------------------------------------
// 0: clear flags + degree counters + scan base
// ---------------------------------------------------------------------------
__global__ void clear_kernel() {
    int i = blockIdx.x * blockDim.x + threadIdx.x;
    if (i == 0) g_total = 0;
    if (i < NMAX) { g_deg[i] = 0; g_flag[i] = 0; }
}

// ---------------------------------------------------------------------------
// 1: mark selected destinations
// ---------------------------------------------------------------------------
__global__ void set_flags_kernel(const int* __restrict__ sel_idx, int n_up) {
    int j = blockIdx.x * blockDim.x + threadIdx.x;
    if (j < n_up) g_flag[sel_idx[j]] = 1;
}

// ---------------------------------------------------------------------------
// 2: count live edges per destination (flags are L2-resident, 400KB)
// ---------------------------------------------------------------------------
__global__ void count_kernel(const int* __restrict__ nidx, int n_edge) {
    int e = blockIdx.x * blockDim.x + threadIdx.x;
    if (e >= n_edge) return;
    const int idx = nidx[e];
    if (idx >= 0 && g_flag[idx]) atomicAdd(&g_deg[idx], 1);
}

// ---------------------------------------------------------------------------
// 3: exclusive scan of degrees -> g_off (block scan + atomic block base;
//    offset ordering is non-deterministic but any valid partition works)
// ---------------------------------------------------------------------------
__global__ void scan_kernel() {
    __shared__ int sh[256];
    __shared__ int base;
    const int t = threadIdx.x;
    const int d = blockIdx.x * 256 + t;
    const int v = (d < NMAX) ? g_deg[d] : 0;
    sh[t] = v;
    __syncthreads();
#pragma unroll
    for (int s = 1; s < 256; s <<= 1) {
        int add = (t >= s) ? sh[t - s] : 0;
        __syncthreads();
        sh[t] += add;
        __syncthreads();
    }
    if (t == 255) base = atomicAdd(&g_total, sh[255]);
    __syncthreads();
    if (d < NMAX) g_off[d] = base + sh[t] - v;   // exclusive
}

// ---------------------------------------------------------------------------
// 4: fill CSR edge records (src, weight). g_off becomes the end cursor.
// ---------------------------------------------------------------------------
__global__ void fill_kernel(const int*   __restrict__ nidx,
                            const float* __restrict__ weights,
                            int n_edge, int K) {
    int e = blockIdx.x * blockDim.x + threadIdx.x;
    if (e >= n_edge) return;
    const int idx = nidx[e];
    if (idx >= 0 && g_flag[idx]) {
        const int pos = atomicAdd(&g_off[idx], 1);
        g_edges[pos] = make_int2(e / K, __float_as_int(weights[e]));
    }
}

// ---------------------------------------------------------------------------
// 5: consume. One warp per destination; register accumulation, no atomics.
//    Writes the NORMALIZED row (divide fused here).
// ---------------------------------------------------------------------------
__global__ void consume_kernel(const float* __restrict__ features, int n) {
    const int d    = (blockIdx.x * blockDim.x + threadIdx.x) >> 5;
    const int lane = threadIdx.x & 31;
    if (d >= n) return;
    if (!g_flag[d]) return;

    const int deg   = g_deg[d];
    const int start = g_off[d] - deg;            // g_off[d] is end after fill

    float4 acc = make_float4(0.f, 0.f, 0.f, 0.f);
    float  wsum = 0.f;
    const float4* feat4 = reinterpret_cast<const float4*>(features);

    for (int base = 0; base < deg; base += 32) {
        const int m = min(32, deg - base);
        int2 rec = make_int2(0, 0);
        if (lane < m) rec = g_edges[start + base + lane];
#pragma unroll 5
        for (int e = 0; e < m; ++e) {
            const int   src = __shfl_sync(0xFFFFFFFFu, rec.x, e);
            const float w   = __int_as_float(__shfl_sync(0xFFFFFFFFu, rec.y, e));
            const float4 f  = feat4[(size_t)src * 32 + lane];
            acc.x += w * f.x; acc.y += w * f.y;
            acc.z += w * f.z; acc.w += w * f.w;
            wsum  += w;
        }
    }

    const float ws  = (wsum > 0.f) ? wsum : 0.001f;
    const float inv = 1.0f / ws;
    reinterpret_cast<float4*>(g_row)[(size_t)d * 32 + lane] =
        make_float4(acc.x * inv, acc.y * inv, acc.z * inv, acc.w * inv);
}

// ---------------------------------------------------------------------------
// 6: gather — pure copy of already-normalized rows (row set is L2-resident)
// ---------------------------------------------------------------------------
__global__ void gather_kernel(const int* __restrict__ sel_idx,
                              float* __restrict__ out, int n_up) {
    const int j    = (blockIdx.x * blockDim.x + threadIdx.x) >> 5;
    const int lane = threadIdx.x & 31;
    if (j >= n_up) return;
    const int idx = sel_idx[j];
    reinterpret_cast<float4*>(out)[(size_t)j * 32 + lane] =
        reinterpret_cast<const float4*>(g_row)[(size_t)idx * 32 + lane];
}

// ---------------------------------------------------------------------------
// Launch
// Inputs: features [N,128] f32, weights_down [N,5] f32,
//         nidx_down [N,5] i32, sel_idx_up [N_UP,1] i32 -> out [N_UP,128] f32
// ---------------------------------------------------------------------------
extern "C" void kernel_launch(void* const* d_in, const int* in_sizes, int n_in,
                              void* d_out, int out_size) {
    const float* features = (const float*)d_in[0];
    const float* weights  = (const float*)d_in[1];
    const int*   nidx     = (const int*)  d_in[2];
    const int*   sel_idx  = (const int*)  d_in[3];
    float*       out      = (float*)d_out;

    const int N      = in_sizes[0] / FDIM;
    const int N_UP   = in_sizes[3];
    const int n_edge = in_sizes[2];              // N * K
    const int K      = n_edge / N;

    clear_kernel<<<(NMAX + 255) / 256, 256>>>();
    set_flags_kernel<<<(N_UP + 255) / 256, 256>>>(sel_idx, N_UP);
    count_kernel<<<(n_edge + 255) / 256, 256>>>(nidx, n_edge);
    scan_kernel<<<(NMAX + 255) / 256, 256>>>();
    fill_kernel<<<(n_edge + 255) / 256, 256>>>(nidx, weights, n_edge, K);

    const int WPB = 8;                            // 8 warps / 256-thread block
    consume_kernel<<<(N + WPB - 1) / WPB, WPB * 32>>>(features, N);
    gather_kernel<<<(N_UP + WPB - 1) / WPB, WPB * 32>>>(sel_idx, out, N_UP);
}

// round 5
// speedup vs baseline: 1.2283x; 1.2283x over previous
#include <cuda_runtime.h>
#include <cstddef>

#define NMAX   400000
#define FDIM   128
#define KNBR   5
#define NUPMAX 100000

// Scratch (static device allocations):
//   g_map[i] : 0 = dead dest; otherwise compact_id + 1
//   g_acc    : compact accumulator rows [<=NUPMAX][128]  (~51 MB, fits L2)
//   g_wsum   : compact weight sums
__device__ int   g_map[NMAX];
__device__ int   g_cnt;
__device__ float g_acc[(size_t)NUPMAX * FDIM];
__device__ float g_wsum[NUPMAX];

// v4 float reduction to global memory (fire-and-forget; sm_90+)
__device__ __forceinline__ void red_add_v4(float* p, float4 v) {
    asm volatile("red.global.add.v4.f32 [%0], {%1,%2,%3,%4};"
                 :: "l"(p), "f"(v.x), "f"(v.y), "f"(v.z), "f"(v.w)
                 : "memory");
}

// ---------------------------------------------------------------------------
// 0: clear map + counter
// ---------------------------------------------------------------------------
__global__ void clear_kernel() {
    int i = blockIdx.x * blockDim.x + threadIdx.x;
    if (i == 0) g_cnt = 0;
    if (i < NMAX) g_map[i] = 0;
}

// ---------------------------------------------------------------------------
// 1: mark selected destinations (duplicates benign)
// ---------------------------------------------------------------------------
__global__ void mark_kernel(const int* __restrict__ sel_idx, int n_up) {
    int j = blockIdx.x * blockDim.x + threadIdx.x;
    if (j < n_up) g_map[sel_idx[j]] = -1;
}

// ---------------------------------------------------------------------------
// 2: assign compact ids to marked dests (order nondeterministic — harmless,
//    ids are an internal permutation; sums land in the right output rows)
// ---------------------------------------------------------------------------
__global__ void assign_kernel() {
    int i = blockIdx.x * blockDim.x + threadIdx.x;
    if (i < NMAX && g_map[i] == -1)
        g_map[i] = atomicAdd(&g_cnt, 1) + 1;
}

// ---------------------------------------------------------------------------
// 3: zero the compact accumulator (also pre-warms it into L2, dirty)
// ---------------------------------------------------------------------------
__global__ void zero_kernel(int n_up) {
    int i = blockIdx.x * blockDim.x + threadIdx.x;
    int total4 = n_up * (FDIM / 4);
    if (i < total4)
        reinterpret_cast<float4*>(g_acc)[i] = make_float4(0.f, 0.f, 0.f, 0.f);
    if (i < n_up) g_wsum[i] = 0.f;
}

// ---------------------------------------------------------------------------
// 4: scatter, one WARP per source row. Atomics go to the compact (L2-resident)
//    accumulator. Lanes 0..4 fetch (idx -> cid, weight) in parallel.
// ---------------------------------------------------------------------------
__global__ void scatter_kernel(const float* __restrict__ features,
                               const float* __restrict__ weights,
                               const int*   __restrict__ nidx,
                               int N) {
    const int warp = (blockIdx.x * blockDim.x + threadIdx.x) >> 5;
    const int lane = threadIdx.x & 31;
    if (warp >= N) return;
    const int i = warp;

    int   my_cid  = -1;
    float my_w    = 0.f;
    int   my_live = 0;
    if (lane < KNBR) {
        const int idx = nidx[i * KNBR + lane];
        if (idx >= 0) {
            const int m = g_map[idx];           // 1.6MB map: L2-resident
            if (m > 0) {
                my_cid  = m - 1;
                my_live = 1;
                my_w    = weights[i * KNBR + lane];
            }
        }
    }
    const unsigned live_mask = __ballot_sync(0xFFFFFFFFu, my_live);
    if (live_mask == 0u) return;                 // ~29% of rows: skip all work

    const float4 f = reinterpret_cast<const float4*>(features)[(size_t)i * 32 + lane];

#pragma unroll
    for (int k = 0; k < KNBR; ++k) {
        if (live_mask & (1u << k)) {
            const int   cid = __shfl_sync(0xFFFFFFFFu, my_cid, k);
            const float wk  = __shfl_sync(0xFFFFFFFFu, my_w,   k);
            float* row = g_acc + (size_t)cid * FDIM + lane * 4;
            red_add_v4(row, make_float4(wk * f.x, wk * f.y, wk * f.z, wk * f.w));
            if (lane == 0) atomicAdd(g_wsum + cid, wk);
        }
    }
}

// ---------------------------------------------------------------------------
// 5: gather + normalize. One warp per output row; reads L2-resident compact
//    rows, streams the output.
// ---------------------------------------------------------------------------
__global__ void gather_kernel(const int* __restrict__ sel_idx,
                              float* __restrict__ out, int n_up) {
    const int j    = (blockIdx.x * blockDim.x + threadIdx.x) >> 5;
    const int lane = threadIdx.x & 31;
    if (j >= n_up) return;
    const int cid = g_map[sel_idx[j]] - 1;       // guaranteed > 0 for sel rows
    const float s0 = g_wsum[cid];
    const float inv = 1.0f / ((s0 > 0.f) ? s0 : 0.001f);
    const float4 f = reinterpret_cast<const float4*>(g_acc)[(size_t)cid * 32 + lane];
    reinterpret_cast<float4*>(out)[(size_t)j * 32 + lane] =
        make_float4(f.x * inv, f.y * inv, f.z * inv, f.w * inv);
}

// ---------------------------------------------------------------------------
// Launch
// Inputs: features [N,128] f32, weights_down [N,5] f32,
//         nidx_down [N,5] i32, sel_idx_up [N_UP,1] i32 -> out [N_UP,128] f32
// ---------------------------------------------------------------------------
extern "C" void kernel_launch(void* const* d_in, const int* in_sizes, int n_in,
                              void* d_out, int out_size) {
    const float* features = (const float*)d_in[0];
    const float* weights  = (const float*)d_in[1];
    const int*   nidx     = (const int*)  d_in[2];
    const int*   sel_idx  = (const int*)  d_in[3];
    float*       out      = (float*)d_out;

    const int N    = in_sizes[0] / FDIM;
    const int N_UP = in_sizes[3];

    clear_kernel<<<(NMAX + 255) / 256, 256>>>();
    mark_kernel<<<(N_UP + 255) / 256, 256>>>(sel_idx, N_UP);
    assign_kernel<<<(NMAX + 255) / 256, 256>>>();
    zero_kernel<<<(N_UP * (FDIM / 4) + 255) / 256, 256>>>(N_UP);

    const int WPB = 8;                            // 8 warps / 256-thread block
    scatter_kernel<<<(N + WPB - 1) / WPB, WPB * 32>>>(features, weights, nidx, N);
    gather_kernel<<<(N_UP + WPB - 1) / WPB, WPB * 32>>>(sel_idx, out, N_UP);
}

// round 6
// speedup vs baseline: 1.2351x; 1.0055x over previous
#include <cuda_runtime.h>
#include <cstddef>

#define NMAX   400000
#define FDIM   128
#define KNBR   5
#define NEDGE  (NMAX * KNBR)
#define NUPMAX 100000

// Scratch (static device allocations):
//   g_map[i]  : 0 = dead dest; -1 = marked; else compact_id + 1
//   g_deg     : live in-degree per compact id
//   g_off     : CSR offset (fill turns it into end cursor)
//   g_edges   : (src, weight-bits) records, grouped by compact dest
//   g_acc     : final normalized rows per compact id (~51 MB, L2-resident)
__device__ int   g_map[NMAX];
__device__ int   g_cnt;
__device__ int   g_deg[NUPMAX];
__device__ int   g_off[NUPMAX];
__device__ int   g_scan_base;
__device__ int2  g_edges[NEDGE];
__device__ float g_acc[(size_t)NUPMAX * FDIM];

// ---------------------------------------------------------------------------
// 0: clear map + per-cid degree + counters
// ---------------------------------------------------------------------------
__global__ void clear_kernel() {
    int i = blockIdx.x * blockDim.x + threadIdx.x;
    if (i == 0) { g_cnt = 0; g_scan_base = 0; }
    if (i < NMAX)   g_map[i] = 0;
    if (i < NUPMAX) g_deg[i] = 0;
}

// ---------------------------------------------------------------------------
// 1: mark selected destinations
// ---------------------------------------------------------------------------
__global__ void mark_kernel(const int* __restrict__ sel_idx, int n_up) {
    int j = blockIdx.x * blockDim.x + threadIdx.x;
    if (j < n_up) g_map[sel_idx[j]] = -1;
}

// ---------------------------------------------------------------------------
// 2: assign compact ids (order nondeterministic; internal permutation only)
// ---------------------------------------------------------------------------
__global__ void assign_kernel() {
    int i = blockIdx.x * blockDim.x + threadIdx.x;
    if (i < NMAX && g_map[i] == -1)
        g_map[i] = atomicAdd(&g_cnt, 1) + 1;
}

// ---------------------------------------------------------------------------
// 3: count live edges per compact dest (map + deg are L2-resident)
// ---------------------------------------------------------------------------
__global__ void count_kernel(const int* __restrict__ nidx, int n_edge) {
    int e = blockIdx.x * blockDim.x + threadIdx.x;
    if (e >= n_edge) return;
    const int idx = nidx[e];
    if (idx >= 0) {
        const int m = g_map[idx];
        if (m > 0) atomicAdd(&g_deg[m - 1], 1);
    }
}

// ---------------------------------------------------------------------------
// 4: exclusive scan over compact degrees (100k) -> g_off
// ---------------------------------------------------------------------------
__global__ void scan_kernel() {
    __shared__ int sh[256];
    __shared__ int base;
    const int t = threadIdx.x;
    const int d = blockIdx.x * 256 + t;
    const int v = (d < NUPMAX) ? g_deg[d] : 0;
    sh[t] = v;
    __syncthreads();
#pragma unroll
    for (int s = 1; s < 256; s <<= 1) {
        int add = (t >= s) ? sh[t - s] : 0;
        __syncthreads();
        sh[t] += add;
        __syncthreads();
    }
    if (t == 255) base = atomicAdd(&g_scan_base, sh[255]);
    __syncthreads();
    if (d < NUPMAX) g_off[d] = base + sh[t] - v;   // exclusive
}

// ---------------------------------------------------------------------------
// 5: fill CSR edge records. g_off becomes the end cursor.
// ---------------------------------------------------------------------------
__global__ void fill_kernel(const int*   __restrict__ nidx,
                            const float* __restrict__ weights,
                            int n_edge, int K) {
    int e = blockIdx.x * blockDim.x + threadIdx.x;
    if (e >= n_edge) return;
    const int idx = nidx[e];
    if (idx >= 0) {
        const int m = g_map[idx];
        if (m > 0) {
            const int pos = atomicAdd(&g_off[m - 1], 1);
            g_edges[pos] = make_int2(e / K, __float_as_int(weights[e]));
        }
    }
}

// ---------------------------------------------------------------------------
// 6: consume. One warp per LIVE compact dest; register accumulation, no
//    atomics, normalization fused. 4-way unrolled edge loop for MLP.
// ---------------------------------------------------------------------------
__global__ void consume_kernel(const float* __restrict__ features) {
    const int cid  = (blockIdx.x * blockDim.x + threadIdx.x) >> 5;
    const int lane = threadIdx.x & 31;
    if (cid >= g_cnt) return;

    const int deg   = g_deg[cid];
    const int start = g_off[cid] - deg;          // g_off is end after fill

    float4 acc = make_float4(0.f, 0.f, 0.f, 0.f);
    float  wsum = 0.f;
    const float4* feat4 = reinterpret_cast<const float4*>(features);

    for (int base = 0; base < deg; base += 32) {
        const int m = min(32, deg - base);
        int2 rec = make_int2(0, 0);
        if (lane < m) rec = g_edges[start + base + lane];

        int e = 0;
        for (; e + 4 <= m; e += 4) {
            const int s0 = __shfl_sync(0xFFFFFFFFu, rec.x, e);
            const int s1 = __shfl_sync(0xFFFFFFFFu, rec.x, e + 1);
            const int s2 = __shfl_sync(0xFFFFFFFFu, rec.x, e + 2);
            const int s3 = __shfl_sync(0xFFFFFFFFu, rec.x, e + 3);
            const float w0 = __int_as_float(__shfl_sync(0xFFFFFFFFu, rec.y, e));
            const float w1 = __int_as_float(__shfl_sync(0xFFFFFFFFu, rec.y, e + 1));
            const float w2 = __int_as_float(__shfl_sync(0xFFFFFFFFu, rec.y, e + 2));
            const float w3 = __int_as_float(__shfl_sync(0xFFFFFFFFu, rec.y, e + 3));
            const float4 f0 = feat4[(size_t)s0 * 32 + lane];   // 4 independent
            const float4 f1 = feat4[(size_t)s1 * 32 + lane];   // loads in flight
            const float4 f2 = feat4[(size_t)s2 * 32 + lane];
            const float4 f3 = feat4[(size_t)s3 * 32 + lane];
            acc.x += w0 * f0.x; acc.y += w0 * f0.y; acc.z += w0 * f0.z; acc.w += w0 * f0.w;
            acc.x += w1 * f1.x; acc.y += w1 * f1.y; acc.z += w1 * f1.z; acc.w += w1 * f1.w;
            acc.x += w2 * f2.x; acc.y += w2 * f2.y; acc.z += w2 * f2.z; acc.w += w2 * f2.w;
            acc.x += w3 * f3.x; acc.y += w3 * f3.y; acc.z += w3 * f3.z; acc.w += w3 * f3.w;
            wsum += w0 + w1 + w2 + w3;
        }
        for (; e < m; ++e) {
            const int   s = __shfl_sync(0xFFFFFFFFu, rec.x, e);
            const float w = __int_as_float(__shfl_sync(0xFFFFFFFFu, rec.y, e));
            const float4 f = feat4[(size_t)s * 32 + lane];
            acc.x += w * f.x; acc.y += w * f.y; acc.z += w * f.z; acc.w += w * f.w;
            wsum += w;
        }
    }

    const float ws  = (wsum > 0.f) ? wsum : 0.001f;
    const float inv = 1.0f / ws;
    reinterpret_cast<float4*>(g_acc)[(size_t)cid * 32 + lane] =
        make_float4(acc.x * inv, acc.y * inv, acc.z * inv, acc.w * inv);
}

// ---------------------------------------------------------------------------
// 7: gather — copy normalized compact rows (L2-resident) to output
// ---------------------------------------------------------------------------
__global__ void gather_kernel(const int* __restrict__ sel_idx,
                              float* __restrict__ out, int n_up) {
    const int j    = (blockIdx.x * blockDim.x + threadIdx.x) >> 5;
    const int lane = threadIdx.x & 31;
    if (j >= n_up) return;
    const int cid = g_map[sel_idx[j]] - 1;
    reinterpret_cast<float4*>(out)[(size_t)j * 32 + lane] =
        reinterpret_cast<const float4*>(g_acc)[(size_t)cid * 32 + lane];
}

// ---------------------------------------------------------------------------
// Launch
// Inputs: features [N,128] f32, weights_down [N,5] f32,
//         nidx_down [N,5] i32, sel_idx_up [N_UP,1] i32 -> out [N_UP,128] f32
// ---------------------------------------------------------------------------
extern "C" void kernel_launch(void* const* d_in, const int* in_sizes, int n_in,
                              void* d_out, int out_size) {
    const float* features = (const float*)d_in[0];
    const float* weights  = (const float*)d_in[1];
    const int*   nidx     = (const int*)  d_in[2];
    const int*   sel_idx  = (const int*)  d_in[3];
    float*       out      = (float*)d_out;

    const int N      = in_sizes[0] / FDIM;
    const int N_UP   = in_sizes[3];
    const int n_edge = in_sizes[2];
    const int K      = n_edge / N;

    clear_kernel<<<(NMAX + 255) / 256, 256>>>();
    mark_kernel<<<(N_UP + 255) / 256, 256>>>(sel_idx, N_UP);
    assign_kernel<<<(NMAX + 255) / 256, 256>>>();
    count_kernel<<<(n_edge + 255) / 256, 256>>>(nidx, n_edge);
    scan_kernel<<<(NUPMAX + 255) / 256, 256>>>();
    fill_kernel<<<(n_edge + 255) / 256, 256>>>(nidx, weights, n_edge, K);

    const int WPB = 8;                            // 8 warps / 256-thread block
    consume_kernel<<<(NUPMAX + WPB - 1) / WPB, WPB * 32>>>(features);
    gather_kernel<<<(N_UP + WPB - 1) / WPB, WPB * 32>>>(sel_idx, out, N_UP);
}

// round 7
// speedup vs baseline: 1.3951x; 1.1295x over previous
#include <cuda_runtime.h>
#include <cstddef>

#define NMAX     400000
#define FDIM     128
#define KNBR     5
#define NUPMAX   100000
#define CAP      32            // per-dest bin capacity (in-degree ~ Poisson(5))
#define MAXSPILL 8192          // provable-correctness overflow path

// Scratch (static device allocations):
//   g_map[i]  : 0 = dead dest; -1 = marked; else compact_id + 1
//   g_deg     : live in-degree per compact id (atomic cursor during fill)
//   g_edges   : fixed bins [cid][CAP] of (src, weight-bits)
//   g_acc     : UNNORMALIZED accumulated rows per compact id
//   g_wsum    : weight sums per compact id
__device__ int   g_map[NMAX];
__device__ int   g_cnt;
__device__ int   g_deg[NUPMAX];
__device__ int2  g_edges[(size_t)NUPMAX * CAP];
__device__ float g_acc[(size_t)NUPMAX * FDIM];
__device__ float g_wsum[NUPMAX];
__device__ int   g_spillcnt;
__device__ int3  g_spill[MAXSPILL];   // (cid, src, weight-bits)

__device__ __forceinline__ void red_add_v4(float* p, float4 v) {
    asm volatile("red.global.add.v4.f32 [%0], {%1,%2,%3,%4};"
                 :: "l"(p), "f"(v.x), "f"(v.y), "f"(v.z), "f"(v.w)
                 : "memory");
}

// ---------------------------------------------------------------------------
// 0: clear map + degree cursors + counters
// ---------------------------------------------------------------------------
__global__ void clear_kernel() {
    int i = blockIdx.x * blockDim.x + threadIdx.x;
    if (i == 0) { g_cnt = 0; g_spillcnt = 0; }
    if (i < NMAX)   g_map[i] = 0;
    if (i < NUPMAX) g_deg[i] = 0;
}

// ---------------------------------------------------------------------------
// 1: mark selected destinations
// ---------------------------------------------------------------------------
__global__ void mark_kernel(const int* __restrict__ sel_idx, int n_up) {
    int j = blockIdx.x * blockDim.x + threadIdx.x;
    if (j < n_up) g_map[sel_idx[j]] = -1;
}

// ---------------------------------------------------------------------------
// 2: assign compact ids (order nondeterministic; internal permutation only)
// ---------------------------------------------------------------------------
__global__ void assign_kernel() {
    int i = blockIdx.x * blockDim.x + threadIdx.x;
    if (i < NMAX && g_map[i] == -1)
        g_map[i] = atomicAdd(&g_cnt, 1) + 1;
}

// ---------------------------------------------------------------------------
// 3: fill fixed-capacity bins in ONE edge pass (no count/scan).
// ---------------------------------------------------------------------------
__global__ void fill_kernel(const int*   __restrict__ nidx,
                            const float* __restrict__ weights,
                            int n_edge, int K) {
    int e = blockIdx.x * blockDim.x + threadIdx.x;
    if (e >= n_edge) return;
    const int idx = nidx[e];
    if (idx < 0) return;
    const int m = g_map[idx];
    if (m <= 0) return;
    const int cid = m - 1;
    const int pos = atomicAdd(&g_deg[cid], 1);
    const int wb  = __float_as_int(weights[e]);
    if (pos < CAP) {
        g_edges[(size_t)cid * CAP + pos] = make_int2(e / K, wb);
    } else {                                      // essentially never taken
        const int s = atomicAdd(&g_spillcnt, 1);
        if (s < MAXSPILL) g_spill[s] = make_int3(cid, e / K, wb);
    }
}

// ---------------------------------------------------------------------------
// 4: consume. One warp per live compact dest. Edge bin load is a single
//    coalesced 256B read; features accumulate in registers; writes the
//    UNNORMALIZED row + wsum (no zeroing needed anywhere).
// ---------------------------------------------------------------------------
__global__ void consume_kernel(const float* __restrict__ features) {
    const int cid  = (blockIdx.x * blockDim.x + threadIdx.x) >> 5;
    const int lane = threadIdx.x & 31;
    if (cid >= g_cnt) return;

    const int m = min(g_deg[cid], CAP);
    int2 rec = make_int2(0, 0);
    if (lane < m) rec = g_edges[(size_t)cid * CAP + lane];

    float4 acc = make_float4(0.f, 0.f, 0.f, 0.f);
    float  wsum = 0.f;
    const float4* feat4 = reinterpret_cast<const float4*>(features);

    int e = 0;
    for (; e + 4 <= m; e += 4) {
        const int s0 = __shfl_sync(0xFFFFFFFFu, rec.x, e);
        const int s1 = __shfl_sync(0xFFFFFFFFu, rec.x, e + 1);
        const int s2 = __shfl_sync(0xFFFFFFFFu, rec.x, e + 2);
        const int s3 = __shfl_sync(0xFFFFFFFFu, rec.x, e + 3);
        const float w0 = __int_as_float(__shfl_sync(0xFFFFFFFFu, rec.y, e));
        const float w1 = __int_as_float(__shfl_sync(0xFFFFFFFFu, rec.y, e + 1));
        const float w2 = __int_as_float(__shfl_sync(0xFFFFFFFFu, rec.y, e + 2));
        const float w3 = __int_as_float(__shfl_sync(0xFFFFFFFFu, rec.y, e + 3));
        const float4 f0 = feat4[(size_t)s0 * 32 + lane];   // 4 loads in flight
        const float4 f1 = feat4[(size_t)s1 * 32 + lane];
        const float4 f2 = feat4[(size_t)s2 * 32 + lane];
        const float4 f3 = feat4[(size_t)s3 * 32 + lane];
        acc.x += w0 * f0.x; acc.y += w0 * f0.y; acc.z += w0 * f0.z; acc.w += w0 * f0.w;
        acc.x += w1 * f1.x; acc.y += w1 * f1.y; acc.z += w1 * f1.z; acc.w += w1 * f1.w;
        acc.x += w2 * f2.x; acc.y += w2 * f2.y; acc.z += w2 * f2.z; acc.w += w2 * f2.w;
        acc.x += w3 * f3.x; acc.y += w3 * f3.y; acc.z += w3 * f3.z; acc.w += w3 * f3.w;
        wsum += w0 + w1 + w2 + w3;
    }
    for (; e < m; ++e) {
        const int   s = __shfl_sync(0xFFFFFFFFu, rec.x, e);
        const float w = __int_as_float(__shfl_sync(0xFFFFFFFFu, rec.y, e));
        const float4 f = feat4[(size_t)s * 32 + lane];
        acc.x += w * f.x; acc.y += w * f.y; acc.z += w * f.z; acc.w += w * f.w;
        wsum += w;
    }

    reinterpret_cast<float4*>(g_acc)[(size_t)cid * 32 + lane] = acc;
    if (lane == 0) g_wsum[cid] = wsum;
}

// ---------------------------------------------------------------------------
// 5: apply spilled edges (normally zero work; correctness backstop).
//    One small grid; warps stride over spill records with fire-forget atomics.
// ---------------------------------------------------------------------------
__global__ void spill_kernel(const float* __restrict__ features) {
    const int nspill = min(g_spillcnt, MAXSPILL);
    const int warp   = threadIdx.x >> 5;
    const int lane   = threadIdx.x & 31;
    for (int s = warp; s < nspill; s += blockDim.x / 32) {
        const int3 r = g_spill[s];
        const float w = __int_as_float(r.z);
        const float4 f = reinterpret_cast<const float4*>(features)[(size_t)r.y * 32 + lane];
        red_add_v4(g_acc + (size_t)r.x * FDIM + lane * 4,
                   make_float4(w * f.x, w * f.y, w * f.z, w * f.w));
        if (lane == 0) atomicAdd(g_wsum + r.x, w);
    }
}

// ---------------------------------------------------------------------------
// 6: gather + normalize. One warp per output row.
// ---------------------------------------------------------------------------
__global__ void gather_kernel(const int* __restrict__ sel_idx,
                              float* __restrict__ out, int n_up) {
    const int j    = (blockIdx.x * blockDim.x + threadIdx.x) >> 5;
    const int lane = threadIdx.x & 31;
    if (j >= n_up) return;
    const int cid = g_map[sel_idx[j]] - 1;
    const float s0 = g_wsum[cid];
    const float inv = 1.0f / ((s0 > 0.f) ? s0 : 0.001f);
    const float4 f = reinterpret_cast<const float4*>(g_acc)[(size_t)cid * 32 + lane];
    reinterpret_cast<float4*>(out)[(size_t)j * 32 + lane] =
        make_float4(f.x * inv, f.y * inv, f.z * inv, f.w * inv);
}

// ---------------------------------------------------------------------------
// Launch
// Inputs: features [N,128] f32, weights_down [N,5] f32,
//         nidx_down [N,5] i32, sel_idx_up [N_UP,1] i32 -> out [N_UP,128] f32
// ---------------------------------------------------------------------------
extern "C" void kernel_launch(void* const* d_in, const int* in_sizes, int n_in,
                              void* d_out, int out_size) {
    const float* features = (const float*)d_in[0];
    const float* weights  = (const float*)d_in[1];
    const int*   nidx     = (const int*)  d_in[2];
    const int*   sel_idx  = (const int*)  d_in[3];
    float*       out      = (float*)d_out;

    const int N      = in_sizes[0] / FDIM;
    const int N_UP   = in_sizes[3];
    const int n_edge = in_sizes[2];
    const int K      = n_edge / N;

    clear_kernel<<<(NMAX + 255) / 256, 256>>>();
    mark_kernel<<<(N_UP + 255) / 256, 256>>>(sel_idx, N_UP);
    assign_kernel<<<(NMAX + 255) / 256, 256>>>();
    fill_kernel<<<(n_edge + 255) / 256, 256>>>(nidx, weights, n_edge, K);

    const int WPB = 8;                            // 8 warps / 256-thread block
    consume_kernel<<<(NUPMAX + WPB - 1) / WPB, WPB * 32>>>(features);
    spill_kernel<<<1, 256>>>(features);
    gather_kernel<<<(N_UP + WPB - 1) / WPB, WPB * 32>>>(sel_idx, out, N_UP);
}

// round 8
// speedup vs baseline: 1.8136x; 1.3000x over previous
#include <cuda_runtime.h>
#include <cstddef>

#define NMAX     400000
#define FDIM     128
#define KNBR     5
#define NUPMAX   100000
#define CAP      32            // per-dest bin capacity (in-degree ~ Poisson(5))
#define MAXSPILL 8192          // provable-correctness overflow path

// Scratch (static device allocations):
//   g_map[i]  : 0 = dead dest; -1 = transient mark; else compact_id + 1
//   g_deg     : live in-degree per compact id (atomic cursor during fill)
//   g_edges   : fixed bins [cid][CAP] of (src, weight-bits)
__device__ int   g_map[NMAX];
__device__ int   g_cnt;
__device__ int   g_deg[NUPMAX];
__device__ int2  g_edges[(size_t)NUPMAX * CAP];
__device__ int   g_spillcnt;
__device__ int3  g_spill[MAXSPILL];   // (cid, src, weight-bits)

// ---------------------------------------------------------------------------
// 0: clear map + degree cursors + counters (vectorized)
// ---------------------------------------------------------------------------
__global__ void clear_kernel() {
    const int i = blockIdx.x * blockDim.x + threadIdx.x;
    if (i == 0) { g_cnt = 0; g_spillcnt = 0; }
    const int4 z = make_int4(0, 0, 0, 0);
    if (i < NMAX / 4)   reinterpret_cast<int4*>(g_map)[i] = z;
    if (i < NUPMAX / 4) reinterpret_cast<int4*>(g_deg)[i] = z;
}

// ---------------------------------------------------------------------------
// 1: fused mark + compact-id assign. CAS winner assigns the id; losers skip.
//    (g_map is only read by later kernels, so the transient -1 is private.)
// ---------------------------------------------------------------------------
__global__ void mark_assign_kernel(const int* __restrict__ sel_idx, int n_up) {
    const int j = blockIdx.x * blockDim.x + threadIdx.x;
    if (j >= n_up) return;
    const int idx = sel_idx[j];
    if (atomicCAS(&g_map[idx], 0, -1) == 0)
        g_map[idx] = atomicAdd(&g_cnt, 1) + 1;
}

// ---------------------------------------------------------------------------
// 2: fill fixed-capacity bins; 4 edges per thread for MLP on the random
//    map lookups (the latency bottleneck observed in R7).
// ---------------------------------------------------------------------------
__global__ void fill_kernel(const int*   __restrict__ nidx,
                            const float* __restrict__ weights,
                            int n_edge, int K) {
    const int t = blockIdx.x * blockDim.x + threadIdx.x;
    const int n4 = n_edge >> 2;
    if (t >= n4) return;

    const int4   i4 = reinterpret_cast<const int4*>(nidx)[t];
    const float4 w4 = reinterpret_cast<const float4*>(weights)[t];
    const int e0 = t * 4;
    int   idx[4] = { i4.x, i4.y, i4.z, i4.w };
    float w[4]   = { w4.x, w4.y, w4.z, w4.w };

    int m[4];
#pragma unroll
    for (int k = 0; k < 4; ++k)                   // 4 independent L2 lookups
        m[k] = (idx[k] >= 0) ? __ldg(&g_map[idx[k]]) : 0;

#pragma unroll
    for (int k = 0; k < 4; ++k) {
        if (m[k] > 0) {
            const int cid = m[k] - 1;
            const int pos = atomicAdd(&g_deg[cid], 1);
            const int src = (e0 + k) / K;
            const int wb  = __float_as_int(w[k]);
            if (pos < CAP) {
                g_edges[(size_t)cid * CAP + pos] = make_int2(src, wb);
            } else {                              // essentially never taken
                const int s = atomicAdd(&g_spillcnt, 1);
                if (s < MAXSPILL) g_spill[s] = make_int3(cid, src, wb);
            }
        }
    }
    // tail edges (n_edge % 4), handled by thread 0 (typically zero work)
    if (t == 0) {
        for (int e = n4 * 4; e < n_edge; ++e) {
            const int idxe = nidx[e];
            if (idxe < 0) continue;
            const int me = g_map[idxe];
            if (me <= 0) continue;
            const int cid = me - 1;
            const int pos = atomicAdd(&g_deg[cid], 1);
            const int wb  = __float_as_int(weights[e]);
            if (pos < CAP) g_edges[(size_t)cid * CAP + pos] = make_int2(e / K, wb);
            else { const int s = atomicAdd(&g_spillcnt, 1);
                   if (s < MAXSPILL) g_spill[s] = make_int3(cid, e / K, wb); }
        }
    }
}

// ---------------------------------------------------------------------------
// 3: fused consume + gather. One warp per OUTPUT row j:
//    resolve cid, load its bin (coalesced 8B/lane), accumulate features in
//    registers, normalize, write out[j] directly. No intermediate arrays.
// ---------------------------------------------------------------------------
__global__ void consume_gather_kernel(const float* __restrict__ features,
                                      const int*   __restrict__ sel_idx,
                                      float* __restrict__ out, int n_up) {
    const int j    = (blockIdx.x * blockDim.x + threadIdx.x) >> 5;
    const int lane = threadIdx.x & 31;
    if (j >= n_up) return;

    const int cid = g_map[sel_idx[j]] - 1;        // sel rows always mapped
    const int deg = g_deg[cid];
    const int m   = min(deg, CAP);

    int2 rec = make_int2(0, 0);
    if (lane < m) rec = g_edges[(size_t)cid * CAP + lane];

    float4 acc  = make_float4(0.f, 0.f, 0.f, 0.f);
    float  wsum = 0.f;
    const float4* feat4 = reinterpret_cast<const float4*>(features);

    int e = 0;
    for (; e + 4 <= m; e += 4) {
        const int s0 = __shfl_sync(0xFFFFFFFFu, rec.x, e);
        const int s1 = __shfl_sync(0xFFFFFFFFu, rec.x, e + 1);
        const int s2 = __shfl_sync(0xFFFFFFFFu, rec.x, e + 2);
        const int s3 = __shfl_sync(0xFFFFFFFFu, rec.x, e + 3);
        const float w0 = __int_as_float(__shfl_sync(0xFFFFFFFFu, rec.y, e));
        const float w1 = __int_as_float(__shfl_sync(0xFFFFFFFFu, rec.y, e + 1));
        const float w2 = __int_as_float(__shfl_sync(0xFFFFFFFFu, rec.y, e + 2));
        const float w3 = __int_as_float(__shfl_sync(0xFFFFFFFFu, rec.y, e + 3));
        const float4 f0 = feat4[(size_t)s0 * 32 + lane];   // 4 loads in flight
        const float4 f1 = feat4[(size_t)s1 * 32 + lane];
        const float4 f2 = feat4[(size_t)s2 * 32 + lane];
        const float4 f3 = feat4[(size_t)s3 * 32 + lane];
        acc.x += w0 * f0.x; acc.y += w0 * f0.y; acc.z += w0 * f0.z; acc.w += w0 * f0.w;
        acc.x += w1 * f1.x; acc.y += w1 * f1.y; acc.z += w1 * f1.z; acc.w += w1 * f1.w;
        acc.x += w2 * f2.x; acc.y += w2 * f2.y; acc.z += w2 * f2.z; acc.w += w2 * f2.w;
        acc.x += w3 * f3.x; acc.y += w3 * f3.y; acc.z += w3 * f3.z; acc.w += w3 * f3.w;
        wsum += w0 + w1 + w2 + w3;
    }
    for (; e < m; ++e) {
        const int   s = __shfl_sync(0xFFFFFFFFu, rec.x, e);
        const float w = __int_as_float(__shfl_sync(0xFFFFFFFFu, rec.y, e));
        const float4 f = feat4[(size_t)s * 32 + lane];
        acc.x += w * f.x; acc.y += w * f.y; acc.z += w * f.z; acc.w += w * f.w;
        wsum += w;
    }

    if (deg > CAP) {                              // correctness backstop
        const int nsp = min(g_spillcnt, MAXSPILL);
        for (int s = 0; s < nsp; ++s) {
            const int3 r = g_spill[s];
            if (r.x == cid) {
                const float w = __int_as_float(r.z);
                const float4 f = feat4[(size_t)r.y * 32 + lane];
                acc.x += w * f.x; acc.y += w * f.y; acc.z += w * f.z; acc.w += w * f.w;
                wsum += w;
            }
        }
    }

    const float ws  = (wsum > 0.f) ? wsum : 0.001f;
    const float inv = 1.0f / ws;
    reinterpret_cast<float4*>(out)[(size_t)j * 32 + lane] =
        make_float4(acc.x * inv, acc.y * inv, acc.z * inv, acc.w * inv);
}

// ---------------------------------------------------------------------------
// Launch
// Inputs: features [N,128] f32, weights_down [N,5] f32,
//         nidx_down [N,5] i32, sel_idx_up [N_UP,1] i32 -> out [N_UP,128] f32
// ---------------------------------------------------------------------------
extern "C" void kernel_launch(void* const* d_in, const int* in_sizes, int n_in,
                              void* d_out, int out_size) {
    const float* features = (const float*)d_in[0];
    const float* weights  = (const float*)d_in[1];
    const int*   nidx     = (const int*)  d_in[2];
    const int*   sel_idx  = (const int*)  d_in[3];
    float*       out      = (float*)d_out;

    const int N      = in_sizes[0] / FDIM;
    const int N_UP   = in_sizes[3];
    const int n_edge = in_sizes[2];
    const int K      = n_edge / N;

    clear_kernel<<<(NMAX / 4 + 255) / 256, 256>>>();
    mark_assign_kernel<<<(N_UP + 255) / 256, 256>>>(sel_idx, N_UP);
    fill_kernel<<<(n_edge / 4 + 255) / 256, 256>>>(nidx, weights, n_edge, K);

    const int WPB = 8;                            // 8 warps / 256-thread block
    consume_gather_kernel<<<(N_UP + WPB - 1) / WPB, WPB * 32>>>(features, sel_idx,
                                                                out, N_UP);
}